// round 1
// baseline (speedup 1.0000x reference)
#include <cuda_runtime.h>

#define N_NODES 100000
#define N_EDGES 1600000
#define D 128
#define NC 64
#define SCAN_BLK 1024
#define SCAN_NB ((N_NODES + SCAN_BLK - 1) / SCAN_BLK)   // 98

// ---------------- scratch (device globals; no runtime allocation) ------------
__device__ int   g_count[N_NODES];
__device__ int   g_off[N_NODES + 1];
__device__ int   g_cur[N_NODES];
__device__ int   g_bsum[SCAN_NB + 1];
__device__ int   g_srcs[N_EDGES];
__device__ float g_agg[(size_t)N_NODES * D];
__device__ float g_h1[(size_t)N_NODES * D];
__device__ float g_h2[(size_t)N_NODES * D];

// ---------------- CSR build --------------------------------------------------
__global__ void k_zero_counts() {
    int i = blockIdx.x * blockDim.x + threadIdx.x;
    if (i < N_NODES) g_count[i] = 0;
}

__global__ void k_count(const int* __restrict__ dst) {
    int e = blockIdx.x * blockDim.x + threadIdx.x;
    if (e < N_EDGES) atomicAdd(&g_count[dst[e]], 1);
}

// block-local exclusive scan (Hillis-Steele), block sums out
__global__ void k_scan_local() {
    __shared__ int sh[SCAN_BLK];
    int i = blockIdx.x * SCAN_BLK + threadIdx.x;
    int v = (i < N_NODES) ? g_count[i] : 0;
    sh[threadIdx.x] = v;
    __syncthreads();
    for (int d = 1; d < SCAN_BLK; d <<= 1) {
        int t = (threadIdx.x >= d) ? sh[threadIdx.x - d] : 0;
        __syncthreads();
        sh[threadIdx.x] += t;
        __syncthreads();
    }
    if (i < N_NODES) g_off[i] = sh[threadIdx.x] - v;   // exclusive within block
    if (threadIdx.x == SCAN_BLK - 1) g_bsum[blockIdx.x] = sh[SCAN_BLK - 1];
}

__global__ void k_scan_bsums() {
    if (threadIdx.x == 0 && blockIdx.x == 0) {
        int acc = 0;
        for (int i = 0; i < SCAN_NB; i++) { int v = g_bsum[i]; g_bsum[i] = acc; acc += v; }
    }
}

__global__ void k_scan_add() {
    int i = blockIdx.x * blockDim.x + threadIdx.x;
    if (i < N_NODES) {
        int o = g_off[i] + g_bsum[i >> 10];
        g_off[i] = o;
        g_cur[i] = o;
    }
    if (i == 0) g_off[N_NODES] = N_EDGES;
}

__global__ void k_fill(const int* __restrict__ src, const int* __restrict__ dst) {
    int e = blockIdx.x * blockDim.x + threadIdx.x;
    if (e < N_EDGES) {
        int d = dst[e];
        int p = atomicAdd(&g_cur[d], 1);
        g_srcs[p] = src[e];
    }
}

// ---------------- mean aggregation (gather, warp per node) -------------------
__global__ void __launch_bounds__(256) k_aggregate(const float* __restrict__ x,
                                                   float* __restrict__ agg) {
    int warp = threadIdx.x >> 5, lane = threadIdx.x & 31;
    int n = blockIdx.x * 8 + warp;
    if (n >= N_NODES) return;
    int beg = g_off[n], end = g_off[n + 1];
    float4 acc = make_float4(0.f, 0.f, 0.f, 0.f);
    int e = beg;
    for (; e + 4 <= end; e += 4) {
        int s0 = g_srcs[e], s1 = g_srcs[e + 1], s2 = g_srcs[e + 2], s3 = g_srcs[e + 3];
        float4 v0 = *(const float4*)(x + (size_t)s0 * D + lane * 4);
        float4 v1 = *(const float4*)(x + (size_t)s1 * D + lane * 4);
        float4 v2 = *(const float4*)(x + (size_t)s2 * D + lane * 4);
        float4 v3 = *(const float4*)(x + (size_t)s3 * D + lane * 4);
        acc.x += v0.x + v1.x + v2.x + v3.x;
        acc.y += v0.y + v1.y + v2.y + v3.y;
        acc.z += v0.z + v1.z + v2.z + v3.z;
        acc.w += v0.w + v1.w + v2.w + v3.w;
    }
    for (; e < end; e++) {
        int s = g_srcs[e];
        float4 v = *(const float4*)(x + (size_t)s * D + lane * 4);
        acc.x += v.x; acc.y += v.y; acc.z += v.z; acc.w += v.w;
    }
    float inv = 1.0f / fmaxf((float)(end - beg), 1.0f);
    acc.x *= inv; acc.y *= inv; acc.z *= inv; acc.w *= inv;
    *(float4*)(agg + (size_t)n * D + lane * 4) = acc;
}

// ---------------- hidden layer: out = relu(xs@Ws + xn@Wn + b) ----------------
// smem: Wcat[256][128] (128KB) + per-warp x tile 8x256 (64KB) = 192KB
__global__ void __launch_bounds__(256, 1) k_layer_hidden(
    const float* __restrict__ xs, const float* __restrict__ xn,
    const float* __restrict__ Ws, const float* __restrict__ Wn,
    const float* __restrict__ bias, float* __restrict__ out) {
    extern __shared__ float smem[];
    float* Wc = smem;                 // [256][128]
    float* xb_all = smem + 256 * D;   // 8 warps * 8 nodes * 256

    int tid = threadIdx.x;
    for (int i = tid; i < 128 * D; i += 256) Wc[i] = Ws[i];
    for (int i = tid; i < 128 * D; i += 256) Wc[128 * D + i] = Wn[i];
    __syncthreads();

    int warp = tid >> 5, lane = tid & 31;
    float* xb = xb_all + warp * 2048;
    float4 bv = *(const float4*)(bias + lane * 4);

    int gw = blockIdx.x * 8 + warp;
    int nw = gridDim.x * 8;
    for (int g = gw; g < N_NODES / 8; g += nw) {
        int n0 = g * 8;
        #pragma unroll
        for (int n = 0; n < 8; n++) {
            float4 a = *(const float4*)(xs + (size_t)(n0 + n) * D + lane * 4);
            float4 c = *(const float4*)(xn + (size_t)(n0 + n) * D + lane * 4);
            *(float4*)(xb + n * 256 + lane * 4) = a;
            *(float4*)(xb + n * 256 + 128 + lane * 4) = c;
        }
        __syncwarp();
        float acc[8][4];
        #pragma unroll
        for (int n = 0; n < 8; n++)
            acc[n][0] = acc[n][1] = acc[n][2] = acc[n][3] = 0.f;
        #pragma unroll 2
        for (int k = 0; k < 256; k++) {
            float4 w = *(const float4*)(Wc + k * D + lane * 4);
            #pragma unroll
            for (int n = 0; n < 8; n++) {
                float xv = xb[n * 256 + k];
                acc[n][0] += w.x * xv;
                acc[n][1] += w.y * xv;
                acc[n][2] += w.z * xv;
                acc[n][3] += w.w * xv;
            }
        }
        __syncwarp();
        #pragma unroll
        for (int n = 0; n < 8; n++) {
            float4 r;
            r.x = fmaxf(acc[n][0] + bv.x, 0.f);
            r.y = fmaxf(acc[n][1] + bv.y, 0.f);
            r.z = fmaxf(acc[n][2] + bv.z, 0.f);
            r.w = fmaxf(acc[n][3] + bv.w, 0.f);
            *(float4*)(out + (size_t)(n0 + n) * D + lane * 4) = r;
        }
    }
}

// ---------------- output layer: out = xs@W + b (no relu, 64 cols) ------------
// smem: W[128][64] (32KB) + per-warp x tile 8x128 (32KB) = 64KB
__global__ void __launch_bounds__(256, 1) k_layer_out(
    const float* __restrict__ xs, const float* __restrict__ W,
    const float* __restrict__ bias, float* __restrict__ out) {
    extern __shared__ float smem[];
    float* Wc = smem;                 // [128][64]
    float* xb_all = smem + D * NC;    // 8 warps * 8 * 128

    int tid = threadIdx.x;
    for (int i = tid; i < D * NC; i += 256) Wc[i] = W[i];
    __syncthreads();

    int warp = tid >> 5, lane = tid & 31;
    float* xb = xb_all + warp * 1024;
    float2 bv = *(const float2*)(bias + lane * 2);

    int gw = blockIdx.x * 8 + warp;
    int nw = gridDim.x * 8;
    for (int g = gw; g < N_NODES / 8; g += nw) {
        int n0 = g * 8;
        #pragma unroll
        for (int n = 0; n < 8; n++) {
            float4 a = *(const float4*)(xs + (size_t)(n0 + n) * D + lane * 4);
            *(float4*)(xb + n * 128 + lane * 4) = a;
        }
        __syncwarp();
        float acc[8][2];
        #pragma unroll
        for (int n = 0; n < 8; n++) acc[n][0] = acc[n][1] = 0.f;
        #pragma unroll 2
        for (int k = 0; k < 128; k++) {
            float2 w = *(const float2*)(Wc + k * NC + lane * 2);
            #pragma unroll
            for (int n = 0; n < 8; n++) {
                float xv = xb[n * 128 + k];
                acc[n][0] += w.x * xv;
                acc[n][1] += w.y * xv;
            }
        }
        __syncwarp();
        #pragma unroll
        for (int n = 0; n < 8; n++) {
            float2 r;
            r.x = acc[n][0] + bv.x;
            r.y = acc[n][1] + bv.y;
            *(float2*)(out + (size_t)(n0 + n) * NC + lane * 2) = r;
        }
    }
}

// ---------------- launch -----------------------------------------------------
extern "C" void kernel_launch(void* const* d_in, const int* in_sizes, int n_in,
                              void* d_out, int out_size) {
    const float* feat = (const float*)d_in[0];
    const int*   src  = (const int*)d_in[1];
    const int*   dst  = (const int*)d_in[2];
    const float* Ws1  = (const float*)d_in[3];
    const float* Wn1  = (const float*)d_in[4];
    const float* b1   = (const float*)d_in[5];
    const float* Ws2  = (const float*)d_in[6];
    const float* Wn2  = (const float*)d_in[7];
    const float* b2   = (const float*)d_in[8];
    const float* Wo   = (const float*)d_in[9];
    const float* bo   = (const float*)d_in[10];
    float* out = (float*)d_out;

    float *p_agg, *p_h1, *p_h2;
    cudaGetSymbolAddress((void**)&p_agg, g_agg);
    cudaGetSymbolAddress((void**)&p_h1, g_h1);
    cudaGetSymbolAddress((void**)&p_h2, g_h2);

    const int SMEM_HID = (256 * D + 8 * 2048) * (int)sizeof(float);  // 192KB
    const int SMEM_OUT = (D * NC + 8 * 1024) * (int)sizeof(float);   // 64KB
    cudaFuncSetAttribute(k_layer_hidden, cudaFuncAttributeMaxDynamicSharedMemorySize, SMEM_HID);
    cudaFuncSetAttribute(k_layer_out, cudaFuncAttributeMaxDynamicSharedMemorySize, SMEM_OUT);

    const int EB = (N_EDGES + 255) / 256;
    const int NB = (N_NODES + 255) / 256;

    // CSR build (once; reused by both layers)
    k_zero_counts<<<NB, 256>>>();
    k_count<<<EB, 256>>>(dst);
    k_scan_local<<<SCAN_NB, SCAN_BLK>>>();
    k_scan_bsums<<<1, 32>>>();
    k_scan_add<<<NB, 256>>>();
    k_fill<<<EB, 256>>>(src, dst);

    // layer 1
    k_aggregate<<<(N_NODES + 7) / 8, 256>>>(feat, p_agg);
    k_layer_hidden<<<148, 256, SMEM_HID>>>(feat, p_agg, Ws1, Wn1, b1, p_h1);

    // layer 2
    k_aggregate<<<(N_NODES + 7) / 8, 256>>>(p_h1, p_agg);
    k_layer_hidden<<<148, 256, SMEM_HID>>>(p_h1, p_agg, Ws2, Wn2, b2, p_h2);

    // output
    k_layer_out<<<148, 256, SMEM_OUT>>>(p_h2, Wo, bo, out);
}

// round 3
// speedup vs baseline: 1.6600x; 1.6600x over previous
#include <cuda_runtime.h>
#include <cstdint>

#define N_NODES 100000
#define N_EDGES 1600000
#define D 128
#define NC 64
#define SCAN_BLK 1024
#define SCAN_NB ((N_NODES + SCAN_BLK - 1) / SCAN_BLK)   // 98
#define TILE_M 128
#define N_TILES ((N_NODES + TILE_M - 1) / TILE_M)       // 782

// ---------------- scratch (device globals; no runtime allocation) ------------
__device__ int   g_count[N_NODES];
__device__ int   g_off[N_NODES + 1];
__device__ int   g_cur[N_NODES];
__device__ int   g_bsum[SCAN_NB + 1];
__device__ int   g_srcs[N_EDGES];
__device__ float g_agg[(size_t)N_NODES * D];
__device__ float g_h1[(size_t)N_NODES * D];
__device__ float g_h2[(size_t)N_NODES * D];

// ---------------- helpers ----------------------------------------------------
__device__ __forceinline__ uint32_t smem_u32(const void* p) {
    uint32_t a;
    asm("{ .reg .u64 t; cvta.to.shared.u64 t, %1; cvt.u32.u64 %0, t; }" : "=r"(a) : "l"(p));
    return a;
}
__device__ __forceinline__ uint32_t f2tf(float f) {
    uint32_t u; asm("cvt.rna.tf32.f32 %0, %1;" : "=r"(u) : "f"(f)); return u;
}
__device__ __forceinline__ void cp16(uint32_t dst, const void* src) {
    asm volatile("cp.async.cg.shared.global [%0], [%1], 16;" :: "r"(dst), "l"(src));
}
#define CP_COMMIT() asm volatile("cp.async.commit_group;" ::: "memory")
#define CP_WAIT1()  asm volatile("cp.async.wait_group 1;" ::: "memory")
#define CP_WAIT0()  asm volatile("cp.async.wait_group 0;" ::: "memory")

// m16n8k8 tf32 MMA, accumulate in place
__device__ __forceinline__ void mma8(float* d, const uint32_t* a, const uint32_t* b) {
    asm volatile(
        "mma.sync.aligned.m16n8k8.row.col.f32.tf32.tf32.f32 "
        "{%0,%1,%2,%3}, {%4,%5,%6,%7}, {%8,%9}, {%0,%1,%2,%3};"
        : "+f"(d[0]), "+f"(d[1]), "+f"(d[2]), "+f"(d[3])
        : "r"(a[0]), "r"(a[1]), "r"(a[2]), "r"(a[3]), "r"(b[0]), "r"(b[1]));
}

// ---------------- CSR build --------------------------------------------------
__global__ void k_zero_counts() {
    int i = blockIdx.x * blockDim.x + threadIdx.x;
    if (i < N_NODES) g_count[i] = 0;
}
__global__ void k_count(const int* __restrict__ dst) {
    int e = blockIdx.x * blockDim.x + threadIdx.x;
    if (e < N_EDGES) atomicAdd(&g_count[dst[e]], 1);
}
__global__ void k_scan_local() {
    __shared__ int sh[SCAN_BLK];
    int i = blockIdx.x * SCAN_BLK + threadIdx.x;
    int v = (i < N_NODES) ? g_count[i] : 0;
    sh[threadIdx.x] = v;
    __syncthreads();
    for (int d = 1; d < SCAN_BLK; d <<= 1) {
        int t = (threadIdx.x >= d) ? sh[threadIdx.x - d] : 0;
        __syncthreads();
        sh[threadIdx.x] += t;
        __syncthreads();
    }
    if (i < N_NODES) g_off[i] = sh[threadIdx.x] - v;
    if (threadIdx.x == SCAN_BLK - 1) g_bsum[blockIdx.x] = sh[SCAN_BLK - 1];
}
__global__ void k_scan_bsums() {
    __shared__ int sh[128];
    int i = threadIdx.x;
    int v = (i < SCAN_NB) ? g_bsum[i] : 0;
    sh[i] = v;
    __syncthreads();
    for (int d = 1; d < 128; d <<= 1) {
        int t = (i >= d) ? sh[i - d] : 0;
        __syncthreads();
        sh[i] += t;
        __syncthreads();
    }
    if (i < SCAN_NB) g_bsum[i] = sh[i] - v;   // exclusive
}
__global__ void k_scan_add() {
    int i = blockIdx.x * blockDim.x + threadIdx.x;
    if (i < N_NODES) {
        int o = g_off[i] + g_bsum[i >> 10];
        g_off[i] = o;
        g_cur[i] = o;
    }
    if (i == 0) g_off[N_NODES] = N_EDGES;
}
__global__ void k_fill(const int* __restrict__ src, const int* __restrict__ dst) {
    int e = blockIdx.x * blockDim.x + threadIdx.x;
    if (e < N_EDGES) {
        int d = dst[e];
        int p = atomicAdd(&g_cur[d], 1);
        g_srcs[p] = src[e];
    }
}

// ---------------- mean aggregation (gather, warp per node) -------------------
__global__ void __launch_bounds__(256) k_aggregate(const float* __restrict__ x,
                                                   float* __restrict__ agg) {
    int warp = threadIdx.x >> 5, lane = threadIdx.x & 31;
    int n = blockIdx.x * 8 + warp;
    if (n >= N_NODES) return;
    int beg = g_off[n], end = g_off[n + 1];
    float4 acc = make_float4(0.f, 0.f, 0.f, 0.f);
    int e = beg;
    for (; e + 4 <= end; e += 4) {
        int s0 = g_srcs[e], s1 = g_srcs[e + 1], s2 = g_srcs[e + 2], s3 = g_srcs[e + 3];
        float4 v0 = *(const float4*)(x + (size_t)s0 * D + lane * 4);
        float4 v1 = *(const float4*)(x + (size_t)s1 * D + lane * 4);
        float4 v2 = *(const float4*)(x + (size_t)s2 * D + lane * 4);
        float4 v3 = *(const float4*)(x + (size_t)s3 * D + lane * 4);
        acc.x += v0.x + v1.x + v2.x + v3.x;
        acc.y += v0.y + v1.y + v2.y + v3.y;
        acc.z += v0.z + v1.z + v2.z + v3.z;
        acc.w += v0.w + v1.w + v2.w + v3.w;
    }
    for (; e < end; e++) {
        int s = g_srcs[e];
        float4 v = *(const float4*)(x + (size_t)s * D + lane * 4);
        acc.x += v.x; acc.y += v.y; acc.z += v.z; acc.w += v.w;
    }
    float inv = 1.0f / fmaxf((float)(end - beg), 1.0f);
    acc.x *= inv; acc.y *= inv; acc.z *= inv; acc.w *= inv;
    *(float4*)(agg + (size_t)n * D + lane * 4) = acc;
}

// ============ hidden layer GEMM: out = relu([xs|xn] @ [Ws;Wn] + b) ===========
// mma.sync tf32 m16n8k8. Tile M=128, N=128, K=256 in 8 chunks of 32.
// smem: bias[128] @0, W tf32 [8][128][36] @512 (144KB), A dbl-buf [2][128][36].
#define H_BIAS 0
#define H_W    512
#define H_A    (512 + 8 * 128 * 36 * 4)       // 512 + 147456 = 147968
#define H_SMEM (H_A + 2 * 128 * 36 * 4)       // + 36864 = 184832

__global__ void __launch_bounds__(256, 1) k_gemm_hidden(
    const float* __restrict__ xs, const float* __restrict__ xn,
    const float* __restrict__ Ws, const float* __restrict__ Wn,
    const float* __restrict__ bias, float* __restrict__ out) {
    extern __shared__ char smem[];
    float*    bsm = (float*)(smem + H_BIAS);
    uint32_t* Wsm = (uint32_t*)(smem + H_W);
    float*    Asm = (float*)(smem + H_A);

    int tid = threadIdx.x, lane = tid & 31, wid = tid >> 5;
    int g = lane >> 2, t = lane & 3;
    int m_base = (wid >> 2) * 64;   // 2 warps in M
    int n_base = (wid & 3) * 32;    // 4 warps in N

    if (tid < 128) bsm[tid] = bias[tid];
    // stage W^T tf32: Wsm[c][n][kl] = W[(c%4)*32+kl][n], c<4 from Ws, else Wn
    for (int idx = tid; idx < 8 * 32 * 128; idx += 256) {
        int n = idx & 127, kl = (idx >> 7) & 31, c = idx >> 12;
        const float* srcW = (c < 4) ? Ws : Wn;
        Wsm[(c * 128 + n) * 36 + kl] = f2tf(srcW[((c & 3) * 32 + kl) * 128 + n]);
    }
    __syncthreads();

    uint32_t a_sb = smem_u32(Asm);
    int row_s = tid >> 1, part = tid & 1;

    for (int tile = blockIdx.x; tile < N_TILES; tile += gridDim.x) {
        int n0 = tile * TILE_M;
        int rows = min(TILE_M, N_NODES - n0);
        if (rows < TILE_M) {
            for (int i = tid; i < 2 * 128 * 36; i += 256) Asm[i] = 0.f;
            __syncthreads();
        }
        // prologue: stage chunk 0 (xs cols 0..31)
        if (row_s < rows) {
            const float* src = xs + (size_t)(n0 + row_s) * D + part * 16;
            uint32_t dst = a_sb + (uint32_t)(row_s * 36 + part * 16) * 4;
            #pragma unroll
            for (int i = 0; i < 4; i++) cp16(dst + i * 16, src + i * 4);
        }
        CP_COMMIT();

        float acc[4][4][4];
        #pragma unroll
        for (int mi = 0; mi < 4; mi++)
            #pragma unroll
            for (int ni = 0; ni < 4; ni++)
                acc[mi][ni][0] = acc[mi][ni][1] = acc[mi][ni][2] = acc[mi][ni][3] = 0.f;

        for (int c = 0; c < 8; c++) {
            if (c + 1 < 8) {
                const float* sp = (c + 1 < 4) ? xs : xn;
                int col0 = ((c + 1) & 3) * 32;
                if (row_s < rows) {
                    const float* src = sp + (size_t)(n0 + row_s) * D + col0 + part * 16;
                    uint32_t dst = a_sb + (uint32_t)(((c + 1) & 1) * 128 * 36 + row_s * 36 + part * 16) * 4;
                    #pragma unroll
                    for (int i = 0; i < 4; i++) cp16(dst + i * 16, src + i * 4);
                }
                CP_COMMIT();
                CP_WAIT1();
            } else {
                CP_WAIT0();
            }
            __syncthreads();

            const float*    Ab = Asm + (c & 1) * 128 * 36;
            const uint32_t* Wb = Wsm + c * 128 * 36;
            #pragma unroll
            for (int ks = 0; ks < 4; ks++) {
                int k = ks * 8;
                uint32_t ar[4][4];
                #pragma unroll
                for (int mi = 0; mi < 4; mi++) {
                    const float* ap = Ab + (m_base + mi * 16 + g) * 36 + k + t;
                    ar[mi][0] = f2tf(ap[0]);
                    ar[mi][1] = f2tf(ap[8 * 36]);
                    ar[mi][2] = f2tf(ap[4]);
                    ar[mi][3] = f2tf(ap[8 * 36 + 4]);
                }
                uint32_t br[4][2];
                #pragma unroll
                for (int ni = 0; ni < 4; ni++) {
                    const uint32_t* bp = Wb + (n_base + ni * 8 + g) * 36 + k + t;
                    br[ni][0] = bp[0];
                    br[ni][1] = bp[4];
                }
                #pragma unroll
                for (int mi = 0; mi < 4; mi++)
                    #pragma unroll
                    for (int ni = 0; ni < 4; ni++)
                        mma8(acc[mi][ni], ar[mi], br[ni]);
            }
            __syncthreads();
        }
        // epilogue: bias + relu, float2 stores
        #pragma unroll
        for (int mi = 0; mi < 4; mi++) {
            int r0 = m_base + mi * 16 + g;
            int r1 = r0 + 8;
            #pragma unroll
            for (int ni = 0; ni < 4; ni++) {
                int col = n_base + ni * 8 + 2 * t;
                float bx = bsm[col], by = bsm[col + 1];
                if (r0 < rows) {
                    float2 v;
                    v.x = fmaxf(acc[mi][ni][0] + bx, 0.f);
                    v.y = fmaxf(acc[mi][ni][1] + by, 0.f);
                    *(float2*)(out + (size_t)(n0 + r0) * D + col) = v;
                }
                if (r1 < rows) {
                    float2 v;
                    v.x = fmaxf(acc[mi][ni][2] + bx, 0.f);
                    v.y = fmaxf(acc[mi][ni][3] + by, 0.f);
                    *(float2*)(out + (size_t)(n0 + r1) * D + col) = v;
                }
            }
        }
        __syncthreads();
    }
}

// ============ output layer GEMM: out = x @ Wo + bo  (N=64, K=128) ============
#define O_BIAS 0
#define O_W    512
#define O_A    (512 + 4 * 64 * 36 * 4)        // 512 + 36864 = 37376
#define O_SMEM (O_A + 2 * 128 * 36 * 4)       // + 36864 = 74240

__global__ void __launch_bounds__(256, 1) k_gemm_out(
    const float* __restrict__ x, const float* __restrict__ Wo,
    const float* __restrict__ bias, float* __restrict__ out) {
    extern __shared__ char smem[];
    float*    bsm = (float*)(smem + O_BIAS);
    uint32_t* Wsm = (uint32_t*)(smem + O_W);
    float*    Asm = (float*)(smem + O_A);

    int tid = threadIdx.x, lane = tid & 31, wid = tid >> 5;
    int g = lane >> 2, t = lane & 3;
    int m_base = (wid >> 1) * 32;   // 4 warps in M, 2 m-tiles each
    int n_base = (wid & 1) * 32;    // 2 warps in N, 4 n-tiles each

    if (tid < 64) bsm[tid] = bias[tid];
    for (int idx = tid; idx < 4 * 32 * 64; idx += 256) {
        int n = idx & 63, kl = (idx >> 6) & 31, c = idx >> 11;
        Wsm[(c * 64 + n) * 36 + kl] = f2tf(Wo[(c * 32 + kl) * 64 + n]);
    }
    __syncthreads();

    uint32_t a_sb = smem_u32(Asm);
    int row_s = tid >> 1, part = tid & 1;

    for (int tile = blockIdx.x; tile < N_TILES; tile += gridDim.x) {
        int n0 = tile * TILE_M;
        int rows = min(TILE_M, N_NODES - n0);
        if (rows < TILE_M) {
            for (int i = tid; i < 2 * 128 * 36; i += 256) Asm[i] = 0.f;
            __syncthreads();
        }
        if (row_s < rows) {
            const float* src = x + (size_t)(n0 + row_s) * D + part * 16;
            uint32_t dst = a_sb + (uint32_t)(row_s * 36 + part * 16) * 4;
            #pragma unroll
            for (int i = 0; i < 4; i++) cp16(dst + i * 16, src + i * 4);
        }
        CP_COMMIT();

        float acc[2][4][4];
        #pragma unroll
        for (int mi = 0; mi < 2; mi++)
            #pragma unroll
            for (int ni = 0; ni < 4; ni++)
                acc[mi][ni][0] = acc[mi][ni][1] = acc[mi][ni][2] = acc[mi][ni][3] = 0.f;

        for (int c = 0; c < 4; c++) {
            if (c + 1 < 4) {
                int col0 = (c + 1) * 32;
                if (row_s < rows) {
                    const float* src = x + (size_t)(n0 + row_s) * D + col0 + part * 16;
                    uint32_t dst = a_sb + (uint32_t)(((c + 1) & 1) * 128 * 36 + row_s * 36 + part * 16) * 4;
                    #pragma unroll
                    for (int i = 0; i < 4; i++) cp16(dst + i * 16, src + i * 4);
                }
                CP_COMMIT();
                CP_WAIT1();
            } else {
                CP_WAIT0();
            }
            __syncthreads();

            const float*    Ab = Asm + (c & 1) * 128 * 36;
            const uint32_t* Wb = Wsm + c * 64 * 36;
            #pragma unroll
            for (int ks = 0; ks < 4; ks++) {
                int k = ks * 8;
                uint32_t ar[2][4];
                #pragma unroll
                for (int mi = 0; mi < 2; mi++) {
                    const float* ap = Ab + (m_base + mi * 16 + g) * 36 + k + t;
                    ar[mi][0] = f2tf(ap[0]);
                    ar[mi][1] = f2tf(ap[8 * 36]);
                    ar[mi][2] = f2tf(ap[4]);
                    ar[mi][3] = f2tf(ap[8 * 36 + 4]);
                }
                uint32_t br[4][2];
                #pragma unroll
                for (int ni = 0; ni < 4; ni++) {
                    const uint32_t* bp = Wb + (n_base + ni * 8 + g) * 36 + k + t;
                    br[ni][0] = bp[0];
                    br[ni][1] = bp[4];
                }
                #pragma unroll
                for (int mi = 0; mi < 2; mi++)
                    #pragma unroll
                    for (int ni = 0; ni < 4; ni++)
                        mma8(acc[mi][ni], ar[mi], br[ni]);
            }
            __syncthreads();
        }
        #pragma unroll
        for (int mi = 0; mi < 2; mi++) {
            int r0 = m_base + mi * 16 + g;
            int r1 = r0 + 8;
            #pragma unroll
            for (int ni = 0; ni < 4; ni++) {
                int col = n_base + ni * 8 + 2 * t;
                float bx = bsm[col], by = bsm[col + 1];
                if (r0 < rows) {
                    float2 v;
                    v.x = acc[mi][ni][0] + bx;
                    v.y = acc[mi][ni][1] + by;
                    *(float2*)(out + (size_t)(n0 + r0) * NC + col) = v;
                }
                if (r1 < rows) {
                    float2 v;
                    v.x = acc[mi][ni][2] + bx;
                    v.y = acc[mi][ni][3] + by;
                    *(float2*)(out + (size_t)(n0 + r1) * NC + col) = v;
                }
            }
        }
        __syncthreads();
    }
}

// ---------------- launch -----------------------------------------------------
extern "C" void kernel_launch(void* const* d_in, const int* in_sizes, int n_in,
                              void* d_out, int out_size) {
    const float* feat = (const float*)d_in[0];
    const int*   src  = (const int*)d_in[1];
    const int*   dst  = (const int*)d_in[2];
    const float* Ws1  = (const float*)d_in[3];
    const float* Wn1  = (const float*)d_in[4];
    const float* b1   = (const float*)d_in[5];
    const float* Ws2  = (const float*)d_in[6];
    const float* Wn2  = (const float*)d_in[7];
    const float* b2   = (const float*)d_in[8];
    const float* Wo   = (const float*)d_in[9];
    const float* bo   = (const float*)d_in[10];
    float* out = (float*)d_out;

    float *p_agg, *p_h1, *p_h2;
    cudaGetSymbolAddress((void**)&p_agg, g_agg);
    cudaGetSymbolAddress((void**)&p_h1, g_h1);
    cudaGetSymbolAddress((void**)&p_h2, g_h2);

    cudaFuncSetAttribute(k_gemm_hidden, cudaFuncAttributeMaxDynamicSharedMemorySize, H_SMEM);
    cudaFuncSetAttribute(k_gemm_out, cudaFuncAttributeMaxDynamicSharedMemorySize, O_SMEM);

    const int EB = (N_EDGES + 255) / 256;
    const int NB = (N_NODES + 255) / 256;

    // CSR build (once; reused by both layers)
    k_zero_counts<<<NB, 256>>>();
    k_count<<<EB, 256>>>(dst);
    k_scan_local<<<SCAN_NB, SCAN_BLK>>>();
    k_scan_bsums<<<1, 128>>>();
    k_scan_add<<<NB, 256>>>();
    k_fill<<<EB, 256>>>(src, dst);

    // layer 1
    k_aggregate<<<(N_NODES + 7) / 8, 256>>>(feat, p_agg);
    k_gemm_hidden<<<148, 256, H_SMEM>>>(feat, p_agg, Ws1, Wn1, b1, p_h1);

    // layer 2
    k_aggregate<<<(N_NODES + 7) / 8, 256>>>(p_h1, p_agg);
    k_gemm_hidden<<<148, 256, H_SMEM>>>(p_h1, p_agg, Ws2, Wn2, b2, p_h2);

    // output
    k_gemm_out<<<148, 256, O_SMEM>>>(p_h2, Wo, bo, out);
}